// round 10
// baseline (speedup 1.0000x reference)
#include <cuda_runtime.h>
#include <math.h>

#define NTOT 32768
#define NP   2048
#define NEV  16
#define AGG_NW 16
#define AGG_THREADS (AGG_NW*32)
#define NBPE 9
#define NODES_PB ((NP + NBPE - 1)/NBPE)
#define HT 128
#define AGG_SMEM (NP*16 + 3*NP*16)
#define PEEL_GAP 32

__device__ float g_x[NTOT*6];
__device__ float g_s[NTOT*3];
__device__ float g_h[NTOT*12];
__device__ float g_agg[NTOT*24];
__device__ float g_y[NTOT*24];

__device__ __forceinline__ float elu1(float v){ return v > 0.f ? v : expm1f(v); }

__device__ __forceinline__ void sh_from_x(const float* xv, int n,
        const float* __restrict__ Ws, const float* __restrict__ bs,
        const float* __restrict__ Wh, const float* __restrict__ bh, int li){
    const float* ws = Ws + li*18;  const float* bsl = bs + li*3;
    const float* wh = Wh + li*72;  const float* bhl = bh + li*12;
#pragma unroll
    for (int c=0; c<3; c++){
        float a = __ldg(&bsl[c]);
#pragma unroll
        for (int d=0; d<6; d++) a = fmaf(xv[d], __ldg(&ws[d*3+c]), a);
        g_s[n*3+c] = a;
    }
#pragma unroll
    for (int c=0; c<12; c++){
        float a = __ldg(&bhl[c]);
#pragma unroll
        for (int d=0; d<6; d++) a = fmaf(xv[d], __ldg(&wh[d*12+c]), a);
        g_h[n*12+c] = a;
    }
}

__global__ void k_embed(const float* __restrict__ x, const float* __restrict__ Win,
                        const float* __restrict__ Ws, const float* __restrict__ bs,
                        const float* __restrict__ Wh, const float* __restrict__ bh){
    int n = blockIdx.x*blockDim.x + threadIdx.x;
    if (n >= NTOT) return;
    float xin[9];
#pragma unroll
    for (int d=0; d<9; d++) xin[d] = x[n*9+d];
    float xv[6];
#pragma unroll
    for (int c=0; c<6; c++){
        float a = 0.f;
#pragma unroll
        for (int d=0; d<9; d++) a = fmaf(xin[d], __ldg(&Win[d*6+c]), a);
        xv[c] = a;
        g_x[n*6+c] = a;
    }
    sh_from_x(xv, n, Ws, bs, Wh, bh, 0);
}

// dist with hoisted -2*s_i terms; identical formula in all passes (bitwise consistent)
__device__ __forceinline__ float distp(float p0, float p1, float p2, float sw, float4 sj){
    return fmaxf(fmaf(p0, sj.x, fmaf(p1, sj.y, fmaf(p2, sj.z, sw + sj.w))), 0.f);
}

// ---------------- GravNet aggregation: coarse Illinois bracket + REDUX-min peel ----------------
__global__ __launch_bounds__(AGG_THREADS, 1)
void k_agg(int k){
    extern __shared__ float smem[];
    float4* sv  = (float4*)smem;
    float4* hv0 = sv + NP;
    float4* hv1 = hv0 + NP;
    float4* hv2 = hv1 + NP;

    int ev  = blockIdx.x / NBPE;
    int sub = blockIdx.x % NBPE;
    const float* se = g_s + (size_t)ev*NP*3;
    const float* he = g_h + (size_t)ev*NP*12;

    for (int j = threadIdx.x; j < NP; j += AGG_THREADS){
        float a = se[j*3+0], b = se[j*3+1], c = se[j*3+2];
        float sq = fmaf(c, c, fmaf(b, b, a*a));
        sv[j] = make_float4(a, b, c, sq);
        const float* hr = he + j*12;
        hv0[j] = make_float4(hr[0], hr[1], hr[2],  hr[3]);
        hv1[j] = make_float4(hr[4], hr[5], hr[6],  hr[7]);
        hv2[j] = make_float4(hr[8], hr[9], hr[10], hr[11]);
    }
    __syncthreads();

    int warp = threadIdx.x >> 5, lane = threadIdx.x & 31;
    unsigned lmlt = (1u << lane) - 1u;
    int base = sub * NODES_PB;
    int cntn = min(NODES_PB, NP - base);

    for (int ni = warp; ni < cntn; ni += AGG_NW){
        int i = base + ni;
        float4 siv = sv[i];
        float p0 = -2.f*siv.x, p1 = -2.f*siv.y, p2 = -2.f*siv.z, sw = siv.w;

        unsigned long long selm = 0ull;
        {
            float f[64];
#pragma unroll
            for (int t=0; t<64; t++){
                f[t] = distp(p0, p1, p2, sw, sv[lane + t*32]);
            }
            unsigned mxu = 0u;
#pragma unroll
            for (int t=0; t<64; t++) mxu = umax(mxu, __float_as_uint(f[t]));
            mxu = __reduce_max_sync(0xFFFFFFFFu, mxu);
            float mx = __uint_as_float(mxu);

            int c0=0,c1=0,c2=0,c3=0;
#pragma unroll
            for (int t=0; t<64; t+=4){
                c0 += (f[t] < mx); c1 += (f[t+1] < mx);
                c2 += (f[t+2] < mx); c3 += (f[t+3] < mx);
            }
            int cMx = __reduce_add_sync(0xFFFFFFFFu, (c0+c1)+(c2+c3));

            float T = mx; float selPiv = 0.f;
            bool exact = false, peel = false;
            float plo = 0.f, phi = 0.f;
            int needk = 0;

            if (cMx == k){ exact = true; selPiv = mx; }
            else if (cMx > k && mxu != 0u){
                float lo = 0.f, hi = mx;
                int cLo = 0, cHi = cMx;
                float wLo = 1.f, wHi = 1.f;
                float kh = (float)k - 0.5f;
                int iter = 0;
                while (__float_as_uint(hi) - __float_as_uint(lo) > 1u){
                    if (cHi - cLo <= PEEL_GAP){
                        peel = true; plo = lo; phi = hi; needk = k - cLo;
                        break;
                    }
                    float piv;
                    if ((iter & 7) == 7){
                        piv = __uint_as_float((__float_as_uint(lo) + __float_as_uint(hi)) >> 1);
                    } else {
                        float fLo = ((float)cLo - kh) * wLo;   // < 0
                        float fHi = ((float)cHi - kh) * wHi;   // > 0
                        piv = (lo*fHi - hi*fLo) / (fHi - fLo);
                    }
                    unsigned pu  = __float_as_uint(piv);
                    unsigned lou = __float_as_uint(lo), hiu = __float_as_uint(hi);
                    if (pu <= lou) pu = lou + 1u;
                    if (pu >= hiu) pu = hiu - 1u;
                    piv = __uint_as_float(pu);
                    iter++;
                    int d0=0,d1=0,d2c=0,d3=0;
#pragma unroll
                    for (int t=0; t<64; t+=4){
                        d0  += (f[t]   < piv);
                        d1  += (f[t+1] < piv);
                        d2c += (f[t+2] < piv);
                        d3  += (f[t+3] < piv);
                    }
                    int c = __reduce_add_sync(0xFFFFFFFFu, (d0+d1)+(d2c+d3));
                    if (c == k){ exact = true; selPiv = piv; break; }
                    if (c < k){ lo = piv; cLo = c; wLo = 1.f; wHi *= 0.5f; }
                    else      { hi = piv; cHi = c; wHi = 1.f; wLo *= 0.5f; }
                }
                if (!exact && !peel) T = lo;   // bracket collapsed to 1 ulp
            }

            if (exact){
#pragma unroll
                for (int t=0; t<64; t++)
                    if (f[t] < selPiv) selm |= (1ull << t);
            } else if (peel){
                // selected below plo; bracket mask in [plo, phi)
                unsigned long long bm = 0ull;
#pragma unroll
                for (int t=0; t<64; t++){
                    bool lt = (f[t] < plo);
                    bool in = (!lt) && (f[t] < phi);
                    if (lt) selm |= (1ull << t);
                    if (in) bm   |= (1ull << t);
                }
                // peel needk smallest from bracket, exact ascending-index on ties
                for (int p = 0; p < needk; p++){
                    unsigned best = 0xFFFFFFFFu; int bt = 0;
                    unsigned long long b = bm;
                    while (b){
                        int t = __ffsll((long long)b) - 1;
                        b &= b - 1ull;
                        float d2 = distp(p0, p1, p2, sw, sv[lane + t*32]);
                        unsigned db = __float_as_uint(d2);
                        if (db < best){ best = db; bt = t; }
                    }
                    unsigned vs = __reduce_min_sync(0xFFFFFFFFu, best);
                    unsigned jk = (best == vs) ? (unsigned)(bt*32 + lane) : 0xFFFFFFFFu;
                    unsigned jm = __reduce_min_sync(0xFFFFFFFFu, jk);
                    if (jk == jm){ bm &= ~(1ull << bt); selm |= (1ull << bt); }
                }
            } else {
                // T path (cMx<k, all-equal, or collapsed bracket): threshold + index-order ties
#pragma unroll
                for (int t=0; t<64; t++)
                    if (f[t] < T) selm |= (1ull << t);
                int m = __popc((unsigned)selm) + __popc((unsigned)(selm >> 32));
                m = __reduce_add_sync(0xFFFFFFFFu, m);
                int tiesleft = k - m;
                if (tiesleft > 0){
                    unsigned long long tm = 0ull;
#pragma unroll
                    for (int t=0; t<64; t++)
                        if (f[t] == T) tm |= (1ull << t);
                    unsigned tl = __reduce_or_sync(0xFFFFFFFFu, (unsigned)tm);
                    unsigned th = __reduce_or_sync(0xFFFFFFFFu, (unsigned)(tm >> 32));
                    unsigned long long anyt = ((unsigned long long)th << 32) | tl;
                    while (tiesleft > 0 && anyt){          // warp-uniform
                        int t = __ffsll((long long)anyt) - 1;
                        anyt &= anyt - 1ull;
                        unsigned tb = __ballot_sync(0xFFFFFFFFu, (tm >> t) & 1ull);
                        int nb = __popc(tb);
                        int take = nb < tiesleft ? nb : tiesleft;
                        if ((tb >> lane) & 1u){
                            if ((int)__popc(tb & lmlt) < take) selm |= (1ull << t);
                        }
                        tiesleft -= take;
                    }
                }
            }
        } // f[] dead here

        float sm[12], mxv[12];
#pragma unroll
        for (int d=0; d<12; d++){ sm[d] = 0.f; mxv[d] = -3.4e38f; }
        unsigned long long rem = selm;
        while (rem){
            int t = __ffsll((long long)rem) - 1;
            rem &= rem - 1ull;
            int j = lane + t*32;
            float d2 = distp(p0, p1, p2, sw, sv[j]);
            float w = __expf(-10.f * d2);
            float4 h0 = hv0[j], h1 = hv1[j], h2 = hv2[j];
            float m;
            m=h0.x*w; sm[0]+=m;  mxv[0]=fmaxf(mxv[0],m);
            m=h0.y*w; sm[1]+=m;  mxv[1]=fmaxf(mxv[1],m);
            m=h0.z*w; sm[2]+=m;  mxv[2]=fmaxf(mxv[2],m);
            m=h0.w*w; sm[3]+=m;  mxv[3]=fmaxf(mxv[3],m);
            m=h1.x*w; sm[4]+=m;  mxv[4]=fmaxf(mxv[4],m);
            m=h1.y*w; sm[5]+=m;  mxv[5]=fmaxf(mxv[5],m);
            m=h1.z*w; sm[6]+=m;  mxv[6]=fmaxf(mxv[6],m);
            m=h1.w*w; sm[7]+=m;  mxv[7]=fmaxf(mxv[7],m);
            m=h2.x*w; sm[8]+=m;  mxv[8]=fmaxf(mxv[8],m);
            m=h2.y*w; sm[9]+=m;  mxv[9]=fmaxf(mxv[9],m);
            m=h2.z*w; sm[10]+=m; mxv[10]=fmaxf(mxv[10],m);
            m=h2.w*w; sm[11]+=m; mxv[11]=fmaxf(mxv[11],m);
        }
#pragma unroll
        for (int o=16; o; o>>=1){
#pragma unroll
            for (int d=0; d<12; d++){
                sm[d]  += __shfl_xor_sync(0xFFFFFFFFu, sm[d], o);
                mxv[d]  = fmaxf(mxv[d], __shfl_xor_sync(0xFFFFFFFFu, mxv[d], o));
            }
        }
        if (lane == 0){
            float invk = 1.f / (float)k;
            float* o = g_agg + ((size_t)ev*NP + i)*24;
#pragma unroll
            for (int d=0; d<12; d++){ o[d] = sm[d]*invk; o[12+d] = mxv[d]; }
        }
    }
}

// -------- fused post + per-event stats + global-exchange (+ next-layer s,h) --------
__global__ __launch_bounds__(512)
void k_pse(const float* __restrict__ Wg1, const float* __restrict__ Wg2,
           const float* __restrict__ bg2, const float* __restrict__ Wp1,
           const float* __restrict__ bp1, const float* __restrict__ Wp2,
           const float* __restrict__ bp2, const float* __restrict__ Wex,
           const float* __restrict__ bex, const float* __restrict__ Ws,
           const float* __restrict__ bs,  const float* __restrict__ Wh,
           const float* __restrict__ bh,  int li){
    __shared__ float red[16][18];
    __shared__ float stats[18];
    int ev  = blockIdx.x;
    int tid = threadIdx.x;
    const float* wg1 = Wg1 + li*144; const float* wg2 = Wg2 + li*576; const float* bgl = bg2 + li*24;
    const float* wp1 = Wp1 + li*162; const float* b1  = bp1 + li*6;
    const float* wp2 = Wp2 + li*36;  const float* b2  = bp2 + li*6;

    float tloc[4][6];
#pragma unroll
    for (int rr=0; rr<4; rr++){
        int n = ev*NP + rr*512 + tid;
        float xv[6], av[24], svv[3];
#pragma unroll
        for (int d=0; d<6;  d++) xv[d]  = g_x[n*6+d];
#pragma unroll
        for (int d=0; d<24; d++) av[d]  = g_agg[n*24+d];
#pragma unroll
        for (int d=0; d<3;  d++) svv[d] = g_s[n*3+d];
        float outv[24];
#pragma unroll
        for (int c=0; c<24; c++){
            float a = __ldg(&bgl[c]);
#pragma unroll
            for (int d=0; d<6;  d++) a = fmaf(xv[d], __ldg(&wg1[d*24+c]), a);
#pragma unroll
            for (int e=0; e<24; e++) a = fmaf(av[e], __ldg(&wg2[e*24+c]), a);
            outv[c] = a;
        }
        float t1[6];
#pragma unroll
        for (int c=0; c<6; c++){
            float a = __ldg(&b1[c]);
#pragma unroll
            for (int d=0; d<24; d++) a = fmaf(outv[d], __ldg(&wp1[d*6+c]), a);
#pragma unroll
            for (int e=0; e<3;  e++) a = fmaf(svv[e], __ldg(&wp1[(24+e)*6+c]), a);
            t1[c] = elu1(a);
        }
#pragma unroll
        for (int c=0; c<6; c++){
            float a = __ldg(&b2[c]);
#pragma unroll
            for (int d=0; d<6; d++) a = fmaf(t1[d], __ldg(&wp2[d*6+c]), a);
            tloc[rr][c] = elu1(a);
        }
    }

    float sm[6], mn[6], mx[6];
#pragma unroll
    for (int d=0; d<6; d++){ sm[d]=0.f; mn[d]=3.4e38f; mx[d]=-3.4e38f; }
#pragma unroll
    for (int rr=0; rr<4; rr++)
#pragma unroll
        for (int d=0; d<6; d++){
            float v = tloc[rr][d];
            sm[d]+=v; mn[d]=fminf(mn[d],v); mx[d]=fmaxf(mx[d],v);
        }
#pragma unroll
    for (int o=16; o; o>>=1){
#pragma unroll
        for (int d=0; d<6; d++){
            sm[d] += __shfl_xor_sync(0xFFFFFFFFu, sm[d], o);
            mn[d]  = fminf(mn[d], __shfl_xor_sync(0xFFFFFFFFu, mn[d], o));
            mx[d]  = fmaxf(mx[d], __shfl_xor_sync(0xFFFFFFFFu, mx[d], o));
        }
    }
    int warp = tid >> 5, lane = tid & 31;
    if (lane == 0){
#pragma unroll
        for (int d=0; d<6; d++){ red[warp][d]=sm[d]; red[warp][6+d]=mn[d]; red[warp][12+d]=mx[d]; }
    }
    __syncthreads();
    if (warp == 0){
        float s6[6], n6[6], x6[6];
        bool valid = lane < 16;
#pragma unroll
        for (int d=0; d<6; d++){
            s6[d] = valid ? red[lane][d]     : 0.f;
            n6[d] = valid ? red[lane][6+d]   : 3.4e38f;
            x6[d] = valid ? red[lane][12+d]  : -3.4e38f;
        }
#pragma unroll
        for (int o=8; o; o>>=1){
#pragma unroll
            for (int d=0; d<6; d++){
                s6[d] += __shfl_xor_sync(0xFFFFFFFFu, s6[d], o);
                n6[d]  = fminf(n6[d], __shfl_xor_sync(0xFFFFFFFFu, n6[d], o));
                x6[d]  = fmaxf(x6[d], __shfl_xor_sync(0xFFFFFFFFu, x6[d], o));
            }
        }
        if (lane == 0){
#pragma unroll
            for (int d=0; d<6; d++){
                stats[d]    = s6[d] * (1.f/(float)NP);
                stats[6+d]  = n6[d];
                stats[12+d] = x6[d];
            }
        }
    }
    __syncthreads();

    const float* w = Wex + li*144; const float* b = bex + li*6;
    float exs[18];
#pragma unroll
    for (int d=0; d<18; d++) exs[d] = stats[d];
#pragma unroll
    for (int rr=0; rr<4; rr++){
        int n = ev*NP + rr*512 + tid;
        float xv[6];
#pragma unroll
        for (int c=0; c<6; c++){
            float a = __ldg(&b[c]);
#pragma unroll
            for (int d=0; d<18; d++) a = fmaf(exs[d], __ldg(&w[d*6+c]), a);
#pragma unroll
            for (int d=0; d<6;  d++) a = fmaf(tloc[rr][d], __ldg(&w[(18+d)*6+c]), a);
            float v = elu1(a);
            xv[c] = v;
            g_x[n*6+c] = v;
            g_y[n*24 + li*6 + c] = v;
        }
        if (li < 3) sh_from_x(xv, n, Ws, bs, Wh, bh, li+1);
    }
}

__global__ __launch_bounds__(HT)
void k_head(const float* __restrict__ Wd0, const float* __restrict__ bd0,
            const float* __restrict__ Wd,  const float* __restrict__ bd,
            const float* __restrict__ Wh1, const float* __restrict__ bh1,
            const float* __restrict__ Wh2, const float* __restrict__ bh2,
            const float* __restrict__ Wh3, const float* __restrict__ bh3,
            const float* __restrict__ Wc,  const float* __restrict__ bc,
            const float* __restrict__ Wb,  const float* __restrict__ bb,
            float* __restrict__ out){
    __shared__ float sact[HT*65];
    int n = blockIdx.x*HT + threadIdx.x;
    float yv[24];
#pragma unroll
    for (int d=0; d<24; d++) yv[d] = g_y[n*24+d];
    float a6[6];
#pragma unroll
    for (int c=0; c<6; c++){
        float a = __ldg(&bd0[c]);
#pragma unroll
        for (int d=0; d<24; d++) a = fmaf(yv[d], __ldg(&Wd0[d*6+c]), a);
        a6[c] = elu1(a);
    }
#pragma unroll
    for (int j=0; j<3; j++){
        float b6[6];
#pragma unroll
        for (int c=0; c<6; c++){
            float a = __ldg(&bd[j*6+c]);
#pragma unroll
            for (int d=0; d<6; d++) a = fmaf(a6[d], __ldg(&Wd[j*36+d*6+c]), a);
            b6[c] = elu1(a);
        }
#pragma unroll
        for (int c=0; c<6; c++) a6[c] = b6[c];
    }
    float* my = sact + threadIdx.x*65;
#pragma unroll 4
    for (int c=0; c<64; c++){
        float a = __ldg(&bh1[c]);
#pragma unroll
        for (int d=0; d<6; d++) a = fmaf(a6[d], __ldg(&Wh1[d*64+c]), a);
        my[c] = elu1(a);
    }
    float acc[64];
#pragma unroll
    for (int c=0; c<64; c++) acc[c] = __ldg(&bh2[c]);
#pragma unroll 1
    for (int d=0; d<64; d++){
        float v = my[d];
#pragma unroll
        for (int c=0; c<64; c++) acc[c] = fmaf(v, __ldg(&Wh2[d*64+c]), acc[c]);
    }
#pragma unroll
    for (int c=0; c<64; c++) my[c] = elu1(acc[c]);
#pragma unroll
    for (int c=0; c<64; c++) acc[c] = __ldg(&bh3[c]);
#pragma unroll 1
    for (int d=0; d<64; d++){
        float v = my[d];
#pragma unroll
        for (int c=0; c<64; c++) acc[c] = fmaf(v, __ldg(&Wh3[d*64+c]), acc[c]);
    }
#pragma unroll
    for (int c=0; c<64; c++) my[c] = acc[c];
    float* o = out + (size_t)n*31;
#pragma unroll 2
    for (int c=0; c<30; c++){
        float a = __ldg(&bc[c]);
#pragma unroll 1
        for (int d=0; d<64; d++) a = fmaf(my[d], __ldg(&Wc[d*30+c]), a);
        o[c] = a;
    }
    {
        float a = __ldg(&bb[0]);
#pragma unroll 1
        for (int d=0; d<64; d++) a = fmaf(my[d], __ldg(&Wb[d]), a);
        o[30] = a;
    }
}

extern "C" void kernel_launch(void* const* d_in, const int* in_sizes, int n_in,
                              void* d_out, int out_size) {
    const float* x    = (const float*)d_in[0];
    const float* Win  = (const float*)d_in[1];
    const float* Ws   = (const float*)d_in[2];
    const float* bs   = (const float*)d_in[3];
    const float* Wh   = (const float*)d_in[4];
    const float* bh   = (const float*)d_in[5];
    const float* Wg1  = (const float*)d_in[6];
    const float* Wg2  = (const float*)d_in[7];
    const float* bg2  = (const float*)d_in[8];
    const float* Wp1  = (const float*)d_in[9];
    const float* bp1  = (const float*)d_in[10];
    const float* Wp2  = (const float*)d_in[11];
    const float* bp2  = (const float*)d_in[12];
    const float* Wex  = (const float*)d_in[13];
    const float* bex  = (const float*)d_in[14];
    const float* Wd0  = (const float*)d_in[15];
    const float* bd0  = (const float*)d_in[16];
    const float* Wd   = (const float*)d_in[17];
    const float* bd   = (const float*)d_in[18];
    const float* Wh1  = (const float*)d_in[19];
    const float* bh1  = (const float*)d_in[20];
    const float* Wh2  = (const float*)d_in[21];
    const float* bh2  = (const float*)d_in[22];
    const float* Wh3  = (const float*)d_in[23];
    const float* bh3  = (const float*)d_in[24];
    const float* Wc   = (const float*)d_in[25];
    const float* bc   = (const float*)d_in[26];
    const float* Wb   = (const float*)d_in[27];
    const float* bb   = (const float*)d_in[28];
    float* out = (float*)d_out;

    cudaFuncSetAttribute(k_agg, cudaFuncAttributeMaxDynamicSharedMemorySize, AGG_SMEM);

    const int KS[4] = {16, 128, 16, 256};
    int nb = (NTOT + 255)/256;

    k_embed<<<nb, 256>>>(x, Win, Ws, bs, Wh, bh);
    for (int li = 0; li < 4; li++){
        k_agg<<<NEV*NBPE, AGG_THREADS, AGG_SMEM>>>(KS[li]);
        k_pse<<<NEV, 512>>>(Wg1, Wg2, bg2, Wp1, bp1, Wp2, bp2,
                            Wex, bex, Ws, bs, Wh, bh, li);
    }
    k_head<<<NTOT/HT, HT>>>(Wd0, bd0, Wd, bd, Wh1, bh1, Wh2, bh2,
                            Wh3, bh3, Wc, bc, Wb, bb, out);
}

// round 11
// speedup vs baseline: 1.3051x; 1.3051x over previous
#include <cuda_runtime.h>
#include <math.h>

#define NTOT 32768
#define NP   2048
#define NEV  16
#define AGG_NW 16
#define AGG_THREADS (AGG_NW*32)
#define NBPE 9
#define NODES_PB ((NP + NBPE - 1)/NBPE)
#define HT 128
#define AGG_SMEM (NP*16 + 3*NP*16 + AGG_NW*32*8)
#define PEEL_GAP 32

__device__ float g_x[NTOT*6];
__device__ float g_s[NTOT*3];
__device__ float g_h[NTOT*12];
__device__ float g_agg[NTOT*24];
__device__ float g_y[NTOT*24];

__device__ __forceinline__ float elu1(float v){ return v > 0.f ? v : expm1f(v); }

__device__ __forceinline__ void sh_from_x(const float* xv, int n,
        const float* __restrict__ Ws, const float* __restrict__ bs,
        const float* __restrict__ Wh, const float* __restrict__ bh, int li){
    const float* ws = Ws + li*18;  const float* bsl = bs + li*3;
    const float* wh = Wh + li*72;  const float* bhl = bh + li*12;
#pragma unroll
    for (int c=0; c<3; c++){
        float a = __ldg(&bsl[c]);
#pragma unroll
        for (int d=0; d<6; d++) a = fmaf(xv[d], __ldg(&ws[d*3+c]), a);
        g_s[n*3+c] = a;
    }
#pragma unroll
    for (int c=0; c<12; c++){
        float a = __ldg(&bhl[c]);
#pragma unroll
        for (int d=0; d<6; d++) a = fmaf(xv[d], __ldg(&wh[d*12+c]), a);
        g_h[n*12+c] = a;
    }
}

__global__ void k_embed(const float* __restrict__ x, const float* __restrict__ Win,
                        const float* __restrict__ Ws, const float* __restrict__ bs,
                        const float* __restrict__ Wh, const float* __restrict__ bh){
    int n = blockIdx.x*blockDim.x + threadIdx.x;
    if (n >= NTOT) return;
    float xin[9];
#pragma unroll
    for (int d=0; d<9; d++) xin[d] = x[n*9+d];
    float xv[6];
#pragma unroll
    for (int c=0; c<6; c++){
        float a = 0.f;
#pragma unroll
        for (int d=0; d<9; d++) a = fmaf(xin[d], __ldg(&Win[d*6+c]), a);
        xv[c] = a;
        g_x[n*6+c] = a;
    }
    sh_from_x(xv, n, Ws, bs, Wh, bh, 0);
}

// dist with hoisted -2*s_i terms; identical formula in all passes (bitwise consistent)
__device__ __forceinline__ float distp(float p0, float p1, float p2, float sw, float4 sj){
    return fmaxf(fmaf(p0, sj.x, fmaf(p1, sj.y, fmaf(p2, sj.z, sw + sj.w))), 0.f);
}

// ---------------- GravNet aggregation: coarse Illinois bracket + butterfly-rank endgame ----------------
__global__ __launch_bounds__(AGG_THREADS, 1)
void k_agg(int k){
    extern __shared__ float smem[];
    float4* sv  = (float4*)smem;
    float4* hv0 = sv + NP;
    float4* hv1 = hv0 + NP;
    float4* hv2 = hv1 + NP;
    unsigned long long* pball = (unsigned long long*)(hv2 + NP);

    int ev  = blockIdx.x / NBPE;
    int sub = blockIdx.x % NBPE;
    const float* se = g_s + (size_t)ev*NP*3;
    const float* he = g_h + (size_t)ev*NP*12;

    for (int j = threadIdx.x; j < NP; j += AGG_THREADS){
        float a = se[j*3+0], b = se[j*3+1], c = se[j*3+2];
        float sq = fmaf(c, c, fmaf(b, b, a*a));
        sv[j] = make_float4(a, b, c, sq);
        const float* hr = he + j*12;
        hv0[j] = make_float4(hr[0], hr[1], hr[2],  hr[3]);
        hv1[j] = make_float4(hr[4], hr[5], hr[6],  hr[7]);
        hv2[j] = make_float4(hr[8], hr[9], hr[10], hr[11]);
    }
    __syncthreads();

    int warp = threadIdx.x >> 5, lane = threadIdx.x & 31;
    unsigned lmlt = (1u << lane) - 1u;
    unsigned long long* pbuf = pball + warp*32;
    int base = sub * NODES_PB;
    int cntn = min(NODES_PB, NP - base);

    for (int ni = warp; ni < cntn; ni += AGG_NW){
        int i = base + ni;
        float4 siv = sv[i];
        float p0 = -2.f*siv.x, p1 = -2.f*siv.y, p2 = -2.f*siv.z, sw = siv.w;

        unsigned long long selm = 0ull;
        {
            float f[64];
#pragma unroll
            for (int t=0; t<64; t++){
                f[t] = distp(p0, p1, p2, sw, sv[lane + t*32]);
            }
            unsigned mxu = 0u;
#pragma unroll
            for (int t=0; t<64; t++) mxu = umax(mxu, __float_as_uint(f[t]));
            mxu = __reduce_max_sync(0xFFFFFFFFu, mxu);
            float mx = __uint_as_float(mxu);

            int c0=0,c1=0,c2=0,c3=0;
#pragma unroll
            for (int t=0; t<64; t+=4){
                c0 += (f[t] < mx); c1 += (f[t+1] < mx);
                c2 += (f[t+2] < mx); c3 += (f[t+3] < mx);
            }
            int cMx = __reduce_add_sync(0xFFFFFFFFu, (c0+c1)+(c2+c3));

            float T = mx; float selPiv = 0.f;
            bool exact = false, endg = false;
            float plo = 0.f, phi = 0.f;
            int needk = 0;

            if (cMx == k){ exact = true; selPiv = mx; }
            else if (cMx > k && mxu != 0u){
                float lo = 0.f, hi = mx;
                int cLo = 0, cHi = cMx;
                float wLo = 1.f, wHi = 1.f;
                float kh = (float)k - 0.5f;
                int iter = 0;
                while (__float_as_uint(hi) - __float_as_uint(lo) > 1u){
                    if (cHi - cLo <= PEEL_GAP){
                        endg = true; plo = lo; phi = hi; needk = k - cLo;
                        break;
                    }
                    float piv;
                    if ((iter & 7) == 7){
                        piv = __uint_as_float((__float_as_uint(lo) + __float_as_uint(hi)) >> 1);
                    } else {
                        float fLo = ((float)cLo - kh) * wLo;   // < 0
                        float fHi = ((float)cHi - kh) * wHi;   // > 0
                        piv = (lo*fHi - hi*fLo) / (fHi - fLo);
                    }
                    unsigned pu  = __float_as_uint(piv);
                    unsigned lou = __float_as_uint(lo), hiu = __float_as_uint(hi);
                    if (pu <= lou) pu = lou + 1u;
                    if (pu >= hiu) pu = hiu - 1u;
                    piv = __uint_as_float(pu);
                    iter++;
                    int d0=0,d1=0,d2c=0,d3=0;
#pragma unroll
                    for (int t=0; t<64; t+=4){
                        d0  += (f[t]   < piv);
                        d1  += (f[t+1] < piv);
                        d2c += (f[t+2] < piv);
                        d3  += (f[t+3] < piv);
                    }
                    int c = __reduce_add_sync(0xFFFFFFFFu, (d0+d1)+(d2c+d3));
                    if (c == k){ exact = true; selPiv = piv; break; }
                    if (c < k){ lo = piv; cLo = c; wLo = 1.f; wHi *= 0.5f; }
                    else      { hi = piv; cHi = c; wHi = 1.f; wLo *= 0.5f; }
                }
                if (!exact && !endg) T = lo;   // bracket collapsed to 1 ulp
            }

            if (exact){
#pragma unroll
                for (int t=0; t<64; t++)
                    if (f[t] < selPiv) selm |= (1ull << t);
            } else if (endg){
                // selected below plo; <=32 bracket elems in [plo, phi)
                unsigned long long bm = 0ull;
#pragma unroll
                for (int t=0; t<64; t++){
                    bool lt = (f[t] < plo);
                    bool in = (!lt) && (f[t] < phi);
                    if (lt) selm |= (1ull << t);
                    if (in) bm   |= (1ull << t);
                }
                // per-lane exclusive offset into the per-warp buffer
                int cnt = __popcll(bm);
                int inc = cnt;
#pragma unroll
                for (int o=1; o<32; o<<=1){
                    int v = __shfl_up_sync(0xFFFFFFFFu, inc, o);
                    if (lane >= o) inc += v;
                }
                int off = inc - cnt;
                int nbr = __shfl_sync(0xFFFFFFFFu, inc, 31);   // total (<= 32)
                // compact: key = (d2_bits << 32) | global_index  -> unique, lax.top_k order
                {
                    unsigned long long b = bm; int o2 = off;
                    while (b){
                        int t = __ffsll((long long)b) - 1;
                        b &= b - 1ull;
                        float d2 = distp(p0, p1, p2, sw, sv[lane + t*32]);
                        pbuf[o2++] = ((unsigned long long)__float_as_uint(d2) << 32)
                                   | (unsigned)(t*32 + lane);
                    }
                }
                __syncwarp();
                // one key per lane; rank by butterfly (all-pairs compare)
                unsigned long long mykey = (lane < nbr) ? pbuf[lane] : 0xFFFFFFFFFFFFFFFFull;
                int rank = 0;
#pragma unroll
                for (int s=1; s<32; s++){
                    unsigned long long o3 = __shfl_xor_sync(0xFFFFFFFFu, mykey, s);
                    rank += (o3 < mykey);
                }
                __syncwarp();
                pbuf[lane] = (lane < nbr && rank < needk) ? 1ull : 0ull;
                __syncwarp();
                // owners mark their selected bracket elements
                {
                    unsigned long long b = bm; int o2 = off;
                    while (b){
                        int t = __ffsll((long long)b) - 1;
                        b &= b - 1ull;
                        if (pbuf[o2]) selm |= (1ull << t);
                        o2++;
                    }
                }
                __syncwarp();
            } else {
                // T path (cMx<k, all-equal, or collapsed bracket): threshold + index-order ties
#pragma unroll
                for (int t=0; t<64; t++)
                    if (f[t] < T) selm |= (1ull << t);
                int m = __popc((unsigned)selm) + __popc((unsigned)(selm >> 32));
                m = __reduce_add_sync(0xFFFFFFFFu, m);
                int tiesleft = k - m;
                if (tiesleft > 0){
                    unsigned long long tm = 0ull;
#pragma unroll
                    for (int t=0; t<64; t++)
                        if (f[t] == T) tm |= (1ull << t);
                    unsigned tl = __reduce_or_sync(0xFFFFFFFFu, (unsigned)tm);
                    unsigned th = __reduce_or_sync(0xFFFFFFFFu, (unsigned)(tm >> 32));
                    unsigned long long anyt = ((unsigned long long)th << 32) | tl;
                    while (tiesleft > 0 && anyt){          // warp-uniform
                        int t = __ffsll((long long)anyt) - 1;
                        anyt &= anyt - 1ull;
                        unsigned tb = __ballot_sync(0xFFFFFFFFu, (tm >> t) & 1ull);
                        int nb = __popc(tb);
                        int take = nb < tiesleft ? nb : tiesleft;
                        if ((tb >> lane) & 1u){
                            if ((int)__popc(tb & lmlt) < take) selm |= (1ull << t);
                        }
                        tiesleft -= take;
                    }
                }
            }
        } // f[] dead here

        float sm[12], mxv[12];
#pragma unroll
        for (int d=0; d<12; d++){ sm[d] = 0.f; mxv[d] = -3.4e38f; }
        unsigned long long rem = selm;
        while (rem){
            int t = __ffsll((long long)rem) - 1;
            rem &= rem - 1ull;
            int j = lane + t*32;
            float d2 = distp(p0, p1, p2, sw, sv[j]);
            float w = __expf(-10.f * d2);
            float4 h0 = hv0[j], h1 = hv1[j], h2 = hv2[j];
            float m;
            m=h0.x*w; sm[0]+=m;  mxv[0]=fmaxf(mxv[0],m);
            m=h0.y*w; sm[1]+=m;  mxv[1]=fmaxf(mxv[1],m);
            m=h0.z*w; sm[2]+=m;  mxv[2]=fmaxf(mxv[2],m);
            m=h0.w*w; sm[3]+=m;  mxv[3]=fmaxf(mxv[3],m);
            m=h1.x*w; sm[4]+=m;  mxv[4]=fmaxf(mxv[4],m);
            m=h1.y*w; sm[5]+=m;  mxv[5]=fmaxf(mxv[5],m);
            m=h1.z*w; sm[6]+=m;  mxv[6]=fmaxf(mxv[6],m);
            m=h1.w*w; sm[7]+=m;  mxv[7]=fmaxf(mxv[7],m);
            m=h2.x*w; sm[8]+=m;  mxv[8]=fmaxf(mxv[8],m);
            m=h2.y*w; sm[9]+=m;  mxv[9]=fmaxf(mxv[9],m);
            m=h2.z*w; sm[10]+=m; mxv[10]=fmaxf(mxv[10],m);
            m=h2.w*w; sm[11]+=m; mxv[11]=fmaxf(mxv[11],m);
        }
#pragma unroll
        for (int o=16; o; o>>=1){
#pragma unroll
            for (int d=0; d<12; d++){
                sm[d]  += __shfl_xor_sync(0xFFFFFFFFu, sm[d], o);
                mxv[d]  = fmaxf(mxv[d], __shfl_xor_sync(0xFFFFFFFFu, mxv[d], o));
            }
        }
        if (lane == 0){
            float invk = 1.f / (float)k;
            float* o = g_agg + ((size_t)ev*NP + i)*24;
#pragma unroll
            for (int d=0; d<12; d++){ o[d] = sm[d]*invk; o[12+d] = mxv[d]; }
        }
    }
}

// -------- fused post + per-event stats + global-exchange (+ next-layer s,h) --------
__global__ __launch_bounds__(512)
void k_pse(const float* __restrict__ Wg1, const float* __restrict__ Wg2,
           const float* __restrict__ bg2, const float* __restrict__ Wp1,
           const float* __restrict__ bp1, const float* __restrict__ Wp2,
           const float* __restrict__ bp2, const float* __restrict__ Wex,
           const float* __restrict__ bex, const float* __restrict__ Ws,
           const float* __restrict__ bs,  const float* __restrict__ Wh,
           const float* __restrict__ bh,  int li){
    __shared__ float red[16][18];
    __shared__ float stats[18];
    int ev  = blockIdx.x;
    int tid = threadIdx.x;
    const float* wg1 = Wg1 + li*144; const float* wg2 = Wg2 + li*576; const float* bgl = bg2 + li*24;
    const float* wp1 = Wp1 + li*162; const float* b1  = bp1 + li*6;
    const float* wp2 = Wp2 + li*36;  const float* b2  = bp2 + li*6;

    float tloc[4][6];
#pragma unroll
    for (int rr=0; rr<4; rr++){
        int n = ev*NP + rr*512 + tid;
        float xv[6], av[24], svv[3];
#pragma unroll
        for (int d=0; d<6;  d++) xv[d]  = g_x[n*6+d];
#pragma unroll
        for (int d=0; d<24; d++) av[d]  = g_agg[n*24+d];
#pragma unroll
        for (int d=0; d<3;  d++) svv[d] = g_s[n*3+d];
        float outv[24];
#pragma unroll
        for (int c=0; c<24; c++){
            float a = __ldg(&bgl[c]);
#pragma unroll
            for (int d=0; d<6;  d++) a = fmaf(xv[d], __ldg(&wg1[d*24+c]), a);
#pragma unroll
            for (int e=0; e<24; e++) a = fmaf(av[e], __ldg(&wg2[e*24+c]), a);
            outv[c] = a;
        }
        float t1[6];
#pragma unroll
        for (int c=0; c<6; c++){
            float a = __ldg(&b1[c]);
#pragma unroll
            for (int d=0; d<24; d++) a = fmaf(outv[d], __ldg(&wp1[d*6+c]), a);
#pragma unroll
            for (int e=0; e<3;  e++) a = fmaf(svv[e], __ldg(&wp1[(24+e)*6+c]), a);
            t1[c] = elu1(a);
        }
#pragma unroll
        for (int c=0; c<6; c++){
            float a = __ldg(&b2[c]);
#pragma unroll
            for (int d=0; d<6; d++) a = fmaf(t1[d], __ldg(&wp2[d*6+c]), a);
            tloc[rr][c] = elu1(a);
        }
    }

    float sm[6], mn[6], mx[6];
#pragma unroll
    for (int d=0; d<6; d++){ sm[d]=0.f; mn[d]=3.4e38f; mx[d]=-3.4e38f; }
#pragma unroll
    for (int rr=0; rr<4; rr++)
#pragma unroll
        for (int d=0; d<6; d++){
            float v = tloc[rr][d];
            sm[d]+=v; mn[d]=fminf(mn[d],v); mx[d]=fmaxf(mx[d],v);
        }
#pragma unroll
    for (int o=16; o; o>>=1){
#pragma unroll
        for (int d=0; d<6; d++){
            sm[d] += __shfl_xor_sync(0xFFFFFFFFu, sm[d], o);
            mn[d]  = fminf(mn[d], __shfl_xor_sync(0xFFFFFFFFu, mn[d], o));
            mx[d]  = fmaxf(mx[d], __shfl_xor_sync(0xFFFFFFFFu, mx[d], o));
        }
    }
    int warp = tid >> 5, lane = tid & 31;
    if (lane == 0){
#pragma unroll
        for (int d=0; d<6; d++){ red[warp][d]=sm[d]; red[warp][6+d]=mn[d]; red[warp][12+d]=mx[d]; }
    }
    __syncthreads();
    if (warp == 0){
        float s6[6], n6[6], x6[6];
        bool valid = lane < 16;
#pragma unroll
        for (int d=0; d<6; d++){
            s6[d] = valid ? red[lane][d]     : 0.f;
            n6[d] = valid ? red[lane][6+d]   : 3.4e38f;
            x6[d] = valid ? red[lane][12+d]  : -3.4e38f;
        }
#pragma unroll
        for (int o=8; o; o>>=1){
#pragma unroll
            for (int d=0; d<6; d++){
                s6[d] += __shfl_xor_sync(0xFFFFFFFFu, s6[d], o);
                n6[d]  = fminf(n6[d], __shfl_xor_sync(0xFFFFFFFFu, n6[d], o));
                x6[d]  = fmaxf(x6[d], __shfl_xor_sync(0xFFFFFFFFu, x6[d], o));
            }
        }
        if (lane == 0){
#pragma unroll
            for (int d=0; d<6; d++){
                stats[d]    = s6[d] * (1.f/(float)NP);
                stats[6+d]  = n6[d];
                stats[12+d] = x6[d];
            }
        }
    }
    __syncthreads();

    const float* w = Wex + li*144; const float* b = bex + li*6;
    float exs[18];
#pragma unroll
    for (int d=0; d<18; d++) exs[d] = stats[d];
#pragma unroll
    for (int rr=0; rr<4; rr++){
        int n = ev*NP + rr*512 + tid;
        float xv[6];
#pragma unroll
        for (int c=0; c<6; c++){
            float a = __ldg(&b[c]);
#pragma unroll
            for (int d=0; d<18; d++) a = fmaf(exs[d], __ldg(&w[d*6+c]), a);
#pragma unroll
            for (int d=0; d<6;  d++) a = fmaf(tloc[rr][d], __ldg(&w[(18+d)*6+c]), a);
            float v = elu1(a);
            xv[c] = v;
            g_x[n*6+c] = v;
            g_y[n*24 + li*6 + c] = v;
        }
        if (li < 3) sh_from_x(xv, n, Ws, bs, Wh, bh, li+1);
    }
}

__global__ __launch_bounds__(HT)
void k_head(const float* __restrict__ Wd0, const float* __restrict__ bd0,
            const float* __restrict__ Wd,  const float* __restrict__ bd,
            const float* __restrict__ Wh1, const float* __restrict__ bh1,
            const float* __restrict__ Wh2, const float* __restrict__ bh2,
            const float* __restrict__ Wh3, const float* __restrict__ bh3,
            const float* __restrict__ Wc,  const float* __restrict__ bc,
            const float* __restrict__ Wb,  const float* __restrict__ bb,
            float* __restrict__ out){
    __shared__ float sact[HT*65];
    int n = blockIdx.x*HT + threadIdx.x;
    float yv[24];
#pragma unroll
    for (int d=0; d<24; d++) yv[d] = g_y[n*24+d];
    float a6[6];
#pragma unroll
    for (int c=0; c<6; c++){
        float a = __ldg(&bd0[c]);
#pragma unroll
        for (int d=0; d<24; d++) a = fmaf(yv[d], __ldg(&Wd0[d*6+c]), a);
        a6[c] = elu1(a);
    }
#pragma unroll
    for (int j=0; j<3; j++){
        float b6[6];
#pragma unroll
        for (int c=0; c<6; c++){
            float a = __ldg(&bd[j*6+c]);
#pragma unroll
            for (int d=0; d<6; d++) a = fmaf(a6[d], __ldg(&Wd[j*36+d*6+c]), a);
            b6[c] = elu1(a);
        }
#pragma unroll
        for (int c=0; c<6; c++) a6[c] = b6[c];
    }
    float* my = sact + threadIdx.x*65;
#pragma unroll 4
    for (int c=0; c<64; c++){
        float a = __ldg(&bh1[c]);
#pragma unroll
        for (int d=0; d<6; d++) a = fmaf(a6[d], __ldg(&Wh1[d*64+c]), a);
        my[c] = elu1(a);
    }
    float acc[64];
#pragma unroll
    for (int c=0; c<64; c++) acc[c] = __ldg(&bh2[c]);
#pragma unroll 1
    for (int d=0; d<64; d++){
        float v = my[d];
#pragma unroll
        for (int c=0; c<64; c++) acc[c] = fmaf(v, __ldg(&Wh2[d*64+c]), acc[c]);
    }
#pragma unroll
    for (int c=0; c<64; c++) my[c] = elu1(acc[c]);
#pragma unroll
    for (int c=0; c<64; c++) acc[c] = __ldg(&bh3[c]);
#pragma unroll 1
    for (int d=0; d<64; d++){
        float v = my[d];
#pragma unroll
        for (int c=0; c<64; c++) acc[c] = fmaf(v, __ldg(&Wh3[d*64+c]), acc[c]);
    }
#pragma unroll
    for (int c=0; c<64; c++) my[c] = acc[c];
    float* o = out + (size_t)n*31;
#pragma unroll 2
    for (int c=0; c<30; c++){
        float a = __ldg(&bc[c]);
#pragma unroll 1
        for (int d=0; d<64; d++) a = fmaf(my[d], __ldg(&Wc[d*30+c]), a);
        o[c] = a;
    }
    {
        float a = __ldg(&bb[0]);
#pragma unroll 1
        for (int d=0; d<64; d++) a = fmaf(my[d], __ldg(&Wb[d]), a);
        o[30] = a;
    }
}

extern "C" void kernel_launch(void* const* d_in, const int* in_sizes, int n_in,
                              void* d_out, int out_size) {
    const float* x    = (const float*)d_in[0];
    const float* Win  = (const float*)d_in[1];
    const float* Ws   = (const float*)d_in[2];
    const float* bs   = (const float*)d_in[3];
    const float* Wh   = (const float*)d_in[4];
    const float* bh   = (const float*)d_in[5];
    const float* Wg1  = (const float*)d_in[6];
    const float* Wg2  = (const float*)d_in[7];
    const float* bg2  = (const float*)d_in[8];
    const float* Wp1  = (const float*)d_in[9];
    const float* bp1  = (const float*)d_in[10];
    const float* Wp2  = (const float*)d_in[11];
    const float* bp2  = (const float*)d_in[12];
    const float* Wex  = (const float*)d_in[13];
    const float* bex  = (const float*)d_in[14];
    const float* Wd0  = (const float*)d_in[15];
    const float* bd0  = (const float*)d_in[16];
    const float* Wd   = (const float*)d_in[17];
    const float* bd   = (const float*)d_in[18];
    const float* Wh1  = (const float*)d_in[19];
    const float* bh1  = (const float*)d_in[20];
    const float* Wh2  = (const float*)d_in[21];
    const float* bh2  = (const float*)d_in[22];
    const float* Wh3  = (const float*)d_in[23];
    const float* bh3  = (const float*)d_in[24];
    const float* Wc   = (const float*)d_in[25];
    const float* bc   = (const float*)d_in[26];
    const float* Wb   = (const float*)d_in[27];
    const float* bb   = (const float*)d_in[28];
    float* out = (float*)d_out;

    cudaFuncSetAttribute(k_agg, cudaFuncAttributeMaxDynamicSharedMemorySize, AGG_SMEM);

    const int KS[4] = {16, 128, 16, 256};
    int nb = (NTOT + 255)/256;

    k_embed<<<nb, 256>>>(x, Win, Ws, bs, Wh, bh);
    for (int li = 0; li < 4; li++){
        k_agg<<<NEV*NBPE, AGG_THREADS, AGG_SMEM>>>(KS[li]);
        k_pse<<<NEV, 512>>>(Wg1, Wg2, bg2, Wp1, bp1, Wp2, bp2,
                            Wex, bex, Ws, bs, Wh, bh, li);
    }
    k_head<<<NTOT/HT, HT>>>(Wd0, bd0, Wd, bd, Wh1, bh1, Wh2, bh2,
                            Wh3, bh3, Wc, bc, Wb, bb, out);
}

// round 12
// speedup vs baseline: 1.3069x; 1.0014x over previous
#include <cuda_runtime.h>
#include <math.h>

#define NTOT 32768
#define NP   2048
#define NEV  16
#define AGG_NW 16
#define AGG_THREADS (AGG_NW*32)
#define NBPE 9
#define NODES_PB ((NP + NBPE - 1)/NBPE)
#define HT 128
#define AGG_SMEM (NP*16 + 3*NP*16 + AGG_NW*32*8)
#define PEEL_GAP 32

__device__ float g_x[NTOT*6];
__device__ float g_s[NTOT*3];
__device__ float g_h[NTOT*12];
__device__ float g_agg[NTOT*24];
__device__ float g_y[NTOT*24];

__device__ __forceinline__ float elu1(float v){ return v > 0.f ? v : expm1f(v); }

__device__ __forceinline__ void sh_from_x(const float* xv, int n,
        const float* __restrict__ Ws, const float* __restrict__ bs,
        const float* __restrict__ Wh, const float* __restrict__ bh, int li){
    const float* ws = Ws + li*18;  const float* bsl = bs + li*3;
    const float* wh = Wh + li*72;  const float* bhl = bh + li*12;
#pragma unroll
    for (int c=0; c<3; c++){
        float a = __ldg(&bsl[c]);
#pragma unroll
        for (int d=0; d<6; d++) a = fmaf(xv[d], __ldg(&ws[d*3+c]), a);
        g_s[n*3+c] = a;
    }
#pragma unroll
    for (int c=0; c<12; c++){
        float a = __ldg(&bhl[c]);
#pragma unroll
        for (int d=0; d<6; d++) a = fmaf(xv[d], __ldg(&wh[d*12+c]), a);
        g_h[n*12+c] = a;
    }
}

__global__ void k_embed(const float* __restrict__ x, const float* __restrict__ Win,
                        const float* __restrict__ Ws, const float* __restrict__ bs,
                        const float* __restrict__ Wh, const float* __restrict__ bh){
    int n = blockIdx.x*blockDim.x + threadIdx.x;
    if (n >= NTOT) return;
    float xin[9];
#pragma unroll
    for (int d=0; d<9; d++) xin[d] = x[n*9+d];
    float xv[6];
#pragma unroll
    for (int c=0; c<6; c++){
        float a = 0.f;
#pragma unroll
        for (int d=0; d<9; d++) a = fmaf(xin[d], __ldg(&Win[d*6+c]), a);
        xv[c] = a;
        g_x[n*6+c] = a;
    }
    sh_from_x(xv, n, Ws, bs, Wh, bh, 0);
}

// dist with hoisted -2*s_i terms; identical formula in all passes (bitwise consistent)
__device__ __forceinline__ float distp(float p0, float p1, float p2, float sw, float4 sj){
    return fmaxf(fmaf(p0, sj.x, fmaf(p1, sj.y, fmaf(p2, sj.z, sw + sj.w))), 0.f);
}

// ---------------- GravNet aggregation: warm-started Illinois bracket + butterfly-rank endgame ----------------
__global__ __launch_bounds__(AGG_THREADS, 1)
void k_agg(int k){
    extern __shared__ float smem[];
    float4* sv  = (float4*)smem;
    float4* hv0 = sv + NP;
    float4* hv1 = hv0 + NP;
    float4* hv2 = hv1 + NP;
    unsigned long long* pball = (unsigned long long*)(hv2 + NP);

    int ev  = blockIdx.x / NBPE;
    int sub = blockIdx.x % NBPE;
    const float* se = g_s + (size_t)ev*NP*3;
    const float* he = g_h + (size_t)ev*NP*12;

    for (int j = threadIdx.x; j < NP; j += AGG_THREADS){
        float a = se[j*3+0], b = se[j*3+1], c = se[j*3+2];
        float sq = fmaf(c, c, fmaf(b, b, a*a));
        sv[j] = make_float4(a, b, c, sq);
        const float* hr = he + j*12;
        hv0[j] = make_float4(hr[0], hr[1], hr[2],  hr[3]);
        hv1[j] = make_float4(hr[4], hr[5], hr[6],  hr[7]);
        hv2[j] = make_float4(hr[8], hr[9], hr[10], hr[11]);
    }
    __syncthreads();

    int warp = threadIdx.x >> 5, lane = threadIdx.x & 31;
    unsigned lmlt = (1u << lane) - 1u;
    unsigned long long* pbuf = pball + warp*32;
    int base = sub * NODES_PB;
    int cntn = min(NODES_PB, NP - base);

    float Tprev = -1.f;   // warm-start threshold from previous node (warp-uniform)

    for (int ni = warp; ni < cntn; ni += AGG_NW){
        int i = base + ni;
        float4 siv = sv[i];
        float p0 = -2.f*siv.x, p1 = -2.f*siv.y, p2 = -2.f*siv.z, sw = siv.w;

        unsigned long long selm = 0ull;
        {
            float f[64];
#pragma unroll
            for (int t=0; t<64; t++){
                f[t] = distp(p0, p1, p2, sw, sv[lane + t*32]);
            }
            unsigned mxu = 0u;
#pragma unroll
            for (int t=0; t<64; t++) mxu = umax(mxu, __float_as_uint(f[t]));
            mxu = __reduce_max_sync(0xFFFFFFFFu, mxu);

            float T = __uint_as_float(mxu);
            float selPiv = 0.f;
            bool exact = false, endg = false;
            float plo = 0.f, phi = 0.f;
            int needk = 0;

            if (mxu != 0u){
                // bracket [0, mx+1ulp): cnt(lo)=0, cnt(hi)=NP >= k always
                float lo = 0.f, hi = __uint_as_float(mxu + 1u);
                int cLo = 0, cHi = NP;
                float wLo = 1.f, wHi = 1.f;
                float kh = (float)k - 0.5f;
                int iter = 0; bool first = true;
                while (__float_as_uint(hi) - __float_as_uint(lo) > 1u){
                    if (cHi - cLo <= PEEL_GAP){
                        endg = true; plo = lo; phi = hi; needk = k - cLo;
                        break;
                    }
                    float piv;
                    if (first && Tprev > 0.f){
                        piv = Tprev;                       // warm start
                    } else if ((iter & 7) == 7){
                        piv = __uint_as_float((__float_as_uint(lo) + __float_as_uint(hi)) >> 1);
                    } else {
                        float fLo = ((float)cLo - kh) * wLo;   // < 0
                        float fHi = ((float)cHi - kh) * wHi;   // > 0
                        piv = (lo*fHi - hi*fLo) / (fHi - fLo);
                    }
                    first = false;
                    unsigned pu  = __float_as_uint(piv);
                    unsigned lou = __float_as_uint(lo), hiu = __float_as_uint(hi);
                    if (pu <= lou) pu = lou + 1u;
                    if (pu >= hiu) pu = hiu - 1u;
                    piv = __uint_as_float(pu);
                    iter++;
                    int d0=0,d1=0,d2c=0,d3=0;
#pragma unroll
                    for (int t=0; t<64; t+=4){
                        d0  += (f[t]   < piv);
                        d1  += (f[t+1] < piv);
                        d2c += (f[t+2] < piv);
                        d3  += (f[t+3] < piv);
                    }
                    int c = __reduce_add_sync(0xFFFFFFFFu, (d0+d1)+(d2c+d3));
                    if (c == k){ exact = true; selPiv = piv; break; }
                    if (c < k){ lo = piv; cLo = c; wLo = 1.f; wHi *= 0.5f; }
                    else      { hi = piv; cHi = c; wHi = 1.f; wLo *= 0.5f; }
                }
                if (!exact && !endg) T = lo;   // bracket collapsed to 1 ulp
            }
            Tprev = exact ? selPiv : (endg ? phi : T);

            if (exact){
#pragma unroll
                for (int t=0; t<64; t++)
                    if (f[t] < selPiv) selm |= (1ull << t);
            } else if (endg){
                // selected below plo; <=32 bracket elems in [plo, phi)
                unsigned long long bm = 0ull;
#pragma unroll
                for (int t=0; t<64; t++){
                    bool lt = (f[t] < plo);
                    bool in = (!lt) && (f[t] < phi);
                    if (lt) selm |= (1ull << t);
                    if (in) bm   |= (1ull << t);
                }
                int cnt = __popcll(bm);
                int inc = cnt;
#pragma unroll
                for (int o=1; o<32; o<<=1){
                    int v = __shfl_up_sync(0xFFFFFFFFu, inc, o);
                    if (lane >= o) inc += v;
                }
                int off = inc - cnt;
                int nbr = __shfl_sync(0xFFFFFFFFu, inc, 31);   // total (<= 32)
                {
                    unsigned long long b = bm; int o2 = off;
                    while (b){
                        int t = __ffsll((long long)b) - 1;
                        b &= b - 1ull;
                        float d2 = distp(p0, p1, p2, sw, sv[lane + t*32]);
                        pbuf[o2++] = ((unsigned long long)__float_as_uint(d2) << 32)
                                   | (unsigned)(t*32 + lane);
                    }
                }
                __syncwarp();
                unsigned long long mykey = (lane < nbr) ? pbuf[lane] : 0xFFFFFFFFFFFFFFFFull;
                int rank = 0;
#pragma unroll
                for (int s=1; s<32; s++){
                    unsigned long long o3 = __shfl_xor_sync(0xFFFFFFFFu, mykey, s);
                    rank += (o3 < mykey);
                }
                __syncwarp();
                pbuf[lane] = (lane < nbr && rank < needk) ? 1ull : 0ull;
                __syncwarp();
                {
                    unsigned long long b = bm; int o2 = off;
                    while (b){
                        int t = __ffsll((long long)b) - 1;
                        b &= b - 1ull;
                        if (pbuf[o2]) selm |= (1ull << t);
                        o2++;
                    }
                }
                __syncwarp();
            } else {
                // T path (all-equal or collapsed bracket): threshold + index-order ties
#pragma unroll
                for (int t=0; t<64; t++)
                    if (f[t] < T) selm |= (1ull << t);
                int m = __popc((unsigned)selm) + __popc((unsigned)(selm >> 32));
                m = __reduce_add_sync(0xFFFFFFFFu, m);
                int tiesleft = k - m;
                if (tiesleft > 0){
                    unsigned long long tm = 0ull;
#pragma unroll
                    for (int t=0; t<64; t++)
                        if (f[t] == T) tm |= (1ull << t);
                    unsigned tl = __reduce_or_sync(0xFFFFFFFFu, (unsigned)tm);
                    unsigned th = __reduce_or_sync(0xFFFFFFFFu, (unsigned)(tm >> 32));
                    unsigned long long anyt = ((unsigned long long)th << 32) | tl;
                    while (tiesleft > 0 && anyt){          // warp-uniform
                        int t = __ffsll((long long)anyt) - 1;
                        anyt &= anyt - 1ull;
                        unsigned tb = __ballot_sync(0xFFFFFFFFu, (tm >> t) & 1ull);
                        int nb = __popc(tb);
                        int take = nb < tiesleft ? nb : tiesleft;
                        if ((tb >> lane) & 1u){
                            if ((int)__popc(tb & lmlt) < take) selm |= (1ull << t);
                        }
                        tiesleft -= take;
                    }
                }
            }
        } // f[] dead here

        float sm[12], mxv[12];
#pragma unroll
        for (int d=0; d<12; d++){ sm[d] = 0.f; mxv[d] = -3.4e38f; }
        unsigned long long rem = selm;
        while (rem){
            int t = __ffsll((long long)rem) - 1;
            rem &= rem - 1ull;
            int j = lane + t*32;
            float d2 = distp(p0, p1, p2, sw, sv[j]);
            float w = __expf(-10.f * d2);
            float4 h0 = hv0[j], h1 = hv1[j], h2 = hv2[j];
            float m;
            m=h0.x*w; sm[0]+=m;  mxv[0]=fmaxf(mxv[0],m);
            m=h0.y*w; sm[1]+=m;  mxv[1]=fmaxf(mxv[1],m);
            m=h0.z*w; sm[2]+=m;  mxv[2]=fmaxf(mxv[2],m);
            m=h0.w*w; sm[3]+=m;  mxv[3]=fmaxf(mxv[3],m);
            m=h1.x*w; sm[4]+=m;  mxv[4]=fmaxf(mxv[4],m);
            m=h1.y*w; sm[5]+=m;  mxv[5]=fmaxf(mxv[5],m);
            m=h1.z*w; sm[6]+=m;  mxv[6]=fmaxf(mxv[6],m);
            m=h1.w*w; sm[7]+=m;  mxv[7]=fmaxf(mxv[7],m);
            m=h2.x*w; sm[8]+=m;  mxv[8]=fmaxf(mxv[8],m);
            m=h2.y*w; sm[9]+=m;  mxv[9]=fmaxf(mxv[9],m);
            m=h2.z*w; sm[10]+=m; mxv[10]=fmaxf(mxv[10],m);
            m=h2.w*w; sm[11]+=m; mxv[11]=fmaxf(mxv[11],m);
        }
#pragma unroll
        for (int o=16; o; o>>=1){
#pragma unroll
            for (int d=0; d<12; d++){
                sm[d]  += __shfl_xor_sync(0xFFFFFFFFu, sm[d], o);
                mxv[d]  = fmaxf(mxv[d], __shfl_xor_sync(0xFFFFFFFFu, mxv[d], o));
            }
        }
        if (lane == 0){
            float invk = 1.f / (float)k;
            float* o = g_agg + ((size_t)ev*NP + i)*24;
#pragma unroll
            for (int d=0; d<12; d++){ o[d] = sm[d]*invk; o[12+d] = mxv[d]; }
        }
    }
}

// -------- fused post + per-event stats + global-exchange (+ next-layer s,h) --------
__global__ __launch_bounds__(512)
void k_pse(const float* __restrict__ Wg1, const float* __restrict__ Wg2,
           const float* __restrict__ bg2, const float* __restrict__ Wp1,
           const float* __restrict__ bp1, const float* __restrict__ Wp2,
           const float* __restrict__ bp2, const float* __restrict__ Wex,
           const float* __restrict__ bex, const float* __restrict__ Ws,
           const float* __restrict__ bs,  const float* __restrict__ Wh,
           const float* __restrict__ bh,  int li){
    __shared__ float red[16][18];
    __shared__ float stats[18];
    int ev  = blockIdx.x;
    int tid = threadIdx.x;
    const float* wg1 = Wg1 + li*144; const float* wg2 = Wg2 + li*576; const float* bgl = bg2 + li*24;
    const float* wp1 = Wp1 + li*162; const float* b1  = bp1 + li*6;
    const float* wp2 = Wp2 + li*36;  const float* b2  = bp2 + li*6;

    float tloc[4][6];
#pragma unroll
    for (int rr=0; rr<4; rr++){
        int n = ev*NP + rr*512 + tid;
        float xv[6], av[24], svv[3];
#pragma unroll
        for (int d=0; d<6;  d++) xv[d]  = g_x[n*6+d];
#pragma unroll
        for (int d=0; d<24; d++) av[d]  = g_agg[n*24+d];
#pragma unroll
        for (int d=0; d<3;  d++) svv[d] = g_s[n*3+d];
        float outv[24];
#pragma unroll
        for (int c=0; c<24; c++){
            float a = __ldg(&bgl[c]);
#pragma unroll
            for (int d=0; d<6;  d++) a = fmaf(xv[d], __ldg(&wg1[d*24+c]), a);
#pragma unroll
            for (int e=0; e<24; e++) a = fmaf(av[e], __ldg(&wg2[e*24+c]), a);
            outv[c] = a;
        }
        float t1[6];
#pragma unroll
        for (int c=0; c<6; c++){
            float a = __ldg(&b1[c]);
#pragma unroll
            for (int d=0; d<24; d++) a = fmaf(outv[d], __ldg(&wp1[d*6+c]), a);
#pragma unroll
            for (int e=0; e<3;  e++) a = fmaf(svv[e], __ldg(&wp1[(24+e)*6+c]), a);
            t1[c] = elu1(a);
        }
#pragma unroll
        for (int c=0; c<6; c++){
            float a = __ldg(&b2[c]);
#pragma unroll
            for (int d=0; d<6; d++) a = fmaf(t1[d], __ldg(&wp2[d*6+c]), a);
            tloc[rr][c] = elu1(a);
        }
    }

    float sm[6], mn[6], mx[6];
#pragma unroll
    for (int d=0; d<6; d++){ sm[d]=0.f; mn[d]=3.4e38f; mx[d]=-3.4e38f; }
#pragma unroll
    for (int rr=0; rr<4; rr++)
#pragma unroll
        for (int d=0; d<6; d++){
            float v = tloc[rr][d];
            sm[d]+=v; mn[d]=fminf(mn[d],v); mx[d]=fmaxf(mx[d],v);
        }
#pragma unroll
    for (int o=16; o; o>>=1){
#pragma unroll
        for (int d=0; d<6; d++){
            sm[d] += __shfl_xor_sync(0xFFFFFFFFu, sm[d], o);
            mn[d]  = fminf(mn[d], __shfl_xor_sync(0xFFFFFFFFu, mn[d], o));
            mx[d]  = fmaxf(mx[d], __shfl_xor_sync(0xFFFFFFFFu, mx[d], o));
        }
    }
    int warp = tid >> 5, lane = tid & 31;
    if (lane == 0){
#pragma unroll
        for (int d=0; d<6; d++){ red[warp][d]=sm[d]; red[warp][6+d]=mn[d]; red[warp][12+d]=mx[d]; }
    }
    __syncthreads();
    if (warp == 0){
        float s6[6], n6[6], x6[6];
        bool valid = lane < 16;
#pragma unroll
        for (int d=0; d<6; d++){
            s6[d] = valid ? red[lane][d]     : 0.f;
            n6[d] = valid ? red[lane][6+d]   : 3.4e38f;
            x6[d] = valid ? red[lane][12+d]  : -3.4e38f;
        }
#pragma unroll
        for (int o=8; o; o>>=1){
#pragma unroll
            for (int d=0; d<6; d++){
                s6[d] += __shfl_xor_sync(0xFFFFFFFFu, s6[d], o);
                n6[d]  = fminf(n6[d], __shfl_xor_sync(0xFFFFFFFFu, n6[d], o));
                x6[d]  = fmaxf(x6[d], __shfl_xor_sync(0xFFFFFFFFu, x6[d], o));
            }
        }
        if (lane == 0){
#pragma unroll
            for (int d=0; d<6; d++){
                stats[d]    = s6[d] * (1.f/(float)NP);
                stats[6+d]  = n6[d];
                stats[12+d] = x6[d];
            }
        }
    }
    __syncthreads();

    const float* w = Wex + li*144; const float* b = bex + li*6;
    float exs[18];
#pragma unroll
    for (int d=0; d<18; d++) exs[d] = stats[d];
#pragma unroll
    for (int rr=0; rr<4; rr++){
        int n = ev*NP + rr*512 + tid;
        float xv[6];
#pragma unroll
        for (int c=0; c<6; c++){
            float a = __ldg(&b[c]);
#pragma unroll
            for (int d=0; d<18; d++) a = fmaf(exs[d], __ldg(&w[d*6+c]), a);
#pragma unroll
            for (int d=0; d<6;  d++) a = fmaf(tloc[rr][d], __ldg(&w[(18+d)*6+c]), a);
            float v = elu1(a);
            xv[c] = v;
            g_x[n*6+c] = v;
            g_y[n*24 + li*6 + c] = v;
        }
        if (li < 3) sh_from_x(xv, n, Ws, bs, Wh, bh, li+1);
    }
}

__global__ __launch_bounds__(HT)
void k_head(const float* __restrict__ Wd0, const float* __restrict__ bd0,
            const float* __restrict__ Wd,  const float* __restrict__ bd,
            const float* __restrict__ Wh1, const float* __restrict__ bh1,
            const float* __restrict__ Wh2, const float* __restrict__ bh2,
            const float* __restrict__ Wh3, const float* __restrict__ bh3,
            const float* __restrict__ Wc,  const float* __restrict__ bc,
            const float* __restrict__ Wb,  const float* __restrict__ bb,
            float* __restrict__ out){
    __shared__ float sact[HT*65];
    int n = blockIdx.x*HT + threadIdx.x;
    float yv[24];
#pragma unroll
    for (int d=0; d<24; d++) yv[d] = g_y[n*24+d];
    float a6[6];
#pragma unroll
    for (int c=0; c<6; c++){
        float a = __ldg(&bd0[c]);
#pragma unroll
        for (int d=0; d<24; d++) a = fmaf(yv[d], __ldg(&Wd0[d*6+c]), a);
        a6[c] = elu1(a);
    }
#pragma unroll
    for (int j=0; j<3; j++){
        float b6[6];
#pragma unroll
        for (int c=0; c<6; c++){
            float a = __ldg(&bd[j*6+c]);
#pragma unroll
            for (int d=0; d<6; d++) a = fmaf(a6[d], __ldg(&Wd[j*36+d*6+c]), a);
            b6[c] = elu1(a);
        }
#pragma unroll
        for (int c=0; c<6; c++) a6[c] = b6[c];
    }
    float* my = sact + threadIdx.x*65;
#pragma unroll 4
    for (int c=0; c<64; c++){
        float a = __ldg(&bh1[c]);
#pragma unroll
        for (int d=0; d<6; d++) a = fmaf(a6[d], __ldg(&Wh1[d*64+c]), a);
        my[c] = elu1(a);
    }
    float acc[64];
#pragma unroll
    for (int c=0; c<64; c++) acc[c] = __ldg(&bh2[c]);
#pragma unroll 1
    for (int d=0; d<64; d++){
        float v = my[d];
#pragma unroll
        for (int c=0; c<64; c++) acc[c] = fmaf(v, __ldg(&Wh2[d*64+c]), acc[c]);
    }
#pragma unroll
    for (int c=0; c<64; c++) my[c] = elu1(acc[c]);
#pragma unroll
    for (int c=0; c<64; c++) acc[c] = __ldg(&bh3[c]);
#pragma unroll 1
    for (int d=0; d<64; d++){
        float v = my[d];
#pragma unroll
        for (int c=0; c<64; c++) acc[c] = fmaf(v, __ldg(&Wh3[d*64+c]), acc[c]);
    }
#pragma unroll
    for (int c=0; c<64; c++) my[c] = acc[c];
    float* o = out + (size_t)n*31;
#pragma unroll 2
    for (int c=0; c<30; c++){
        float a = __ldg(&bc[c]);
#pragma unroll 1
        for (int d=0; d<64; d++) a = fmaf(my[d], __ldg(&Wc[d*30+c]), a);
        o[c] = a;
    }
    {
        float a = __ldg(&bb[0]);
#pragma unroll 1
        for (int d=0; d<64; d++) a = fmaf(my[d], __ldg(&Wb[d]), a);
        o[30] = a;
    }
}

extern "C" void kernel_launch(void* const* d_in, const int* in_sizes, int n_in,
                              void* d_out, int out_size) {
    const float* x    = (const float*)d_in[0];
    const float* Win  = (const float*)d_in[1];
    const float* Ws   = (const float*)d_in[2];
    const float* bs   = (const float*)d_in[3];
    const float* Wh   = (const float*)d_in[4];
    const float* bh   = (const float*)d_in[5];
    const float* Wg1  = (const float*)d_in[6];
    const float* Wg2  = (const float*)d_in[7];
    const float* bg2  = (const float*)d_in[8];
    const float* Wp1  = (const float*)d_in[9];
    const float* bp1  = (const float*)d_in[10];
    const float* Wp2  = (const float*)d_in[11];
    const float* bp2  = (const float*)d_in[12];
    const float* Wex  = (const float*)d_in[13];
    const float* bex  = (const float*)d_in[14];
    const float* Wd0  = (const float*)d_in[15];
    const float* bd0  = (const float*)d_in[16];
    const float* Wd   = (const float*)d_in[17];
    const float* bd   = (const float*)d_in[18];
    const float* Wh1  = (const float*)d_in[19];
    const float* bh1  = (const float*)d_in[20];
    const float* Wh2  = (const float*)d_in[21];
    const float* bh2  = (const float*)d_in[22];
    const float* Wh3  = (const float*)d_in[23];
    const float* bh3  = (const float*)d_in[24];
    const float* Wc   = (const float*)d_in[25];
    const float* bc   = (const float*)d_in[26];
    const float* Wb   = (const float*)d_in[27];
    const float* bb   = (const float*)d_in[28];
    float* out = (float*)d_out;

    cudaFuncSetAttribute(k_agg, cudaFuncAttributeMaxDynamicSharedMemorySize, AGG_SMEM);

    const int KS[4] = {16, 128, 16, 256};
    int nb = (NTOT + 255)/256;

    k_embed<<<nb, 256>>>(x, Win, Ws, bs, Wh, bh);
    for (int li = 0; li < 4; li++){
        k_agg<<<NEV*NBPE, AGG_THREADS, AGG_SMEM>>>(KS[li]);
        k_pse<<<NEV, 512>>>(Wg1, Wg2, bg2, Wp1, bp1, Wp2, bp2,
                            Wex, bex, Ws, bs, Wh, bh, li);
    }
    k_head<<<NTOT/HT, HT>>>(Wd0, bd0, Wd, bd, Wh1, bh1, Wh2, bh2,
                            Wh3, bh3, Wc, bc, Wb, bb, out);
}

// round 13
// speedup vs baseline: 1.4942x; 1.1433x over previous
#include <cuda_runtime.h>
#include <math.h>

#define NTOT 32768
#define NP   2048
#define NEV  16
#define AGG_NW 16
#define AGG_THREADS (AGG_NW*32)
#define NBPE 9
#define NODES_PB ((NP + NBPE - 1)/NBPE)
#define HT 128
#define AGG_SMEM (NP*16 + 3*NP*16 + AGG_NW*32*8)
#define PEEL_GAP 32

__device__ float g_x[NTOT*6];
__device__ float g_s[NTOT*3];
__device__ float g_h[NTOT*12];
__device__ float g_agg[NTOT*24];
__device__ float g_t[NTOT*6];
__device__ float g_stats[NEV*18];
__device__ float g_y[NTOT*24];

__device__ __forceinline__ float elu1(float v){ return v > 0.f ? v : expm1f(v); }

__device__ __forceinline__ void sh_from_x(const float* xv, int n,
        const float* __restrict__ Ws, const float* __restrict__ bs,
        const float* __restrict__ Wh, const float* __restrict__ bh, int li){
    const float* ws = Ws + li*18;  const float* bsl = bs + li*3;
    const float* wh = Wh + li*72;  const float* bhl = bh + li*12;
#pragma unroll
    for (int c=0; c<3; c++){
        float a = __ldg(&bsl[c]);
#pragma unroll
        for (int d=0; d<6; d++) a = fmaf(xv[d], __ldg(&ws[d*3+c]), a);
        g_s[n*3+c] = a;
    }
#pragma unroll
    for (int c=0; c<12; c++){
        float a = __ldg(&bhl[c]);
#pragma unroll
        for (int d=0; d<6; d++) a = fmaf(xv[d], __ldg(&wh[d*12+c]), a);
        g_h[n*12+c] = a;
    }
}

__global__ void k_embed(const float* __restrict__ x, const float* __restrict__ Win,
                        const float* __restrict__ Ws, const float* __restrict__ bs,
                        const float* __restrict__ Wh, const float* __restrict__ bh){
    int n = blockIdx.x*blockDim.x + threadIdx.x;
    if (n >= NTOT) return;
    float xin[9];
#pragma unroll
    for (int d=0; d<9; d++) xin[d] = x[n*9+d];
    float xv[6];
#pragma unroll
    for (int c=0; c<6; c++){
        float a = 0.f;
#pragma unroll
        for (int d=0; d<9; d++) a = fmaf(xin[d], __ldg(&Win[d*6+c]), a);
        xv[c] = a;
        g_x[n*6+c] = a;
    }
    sh_from_x(xv, n, Ws, bs, Wh, bh, 0);
}

__device__ __forceinline__ float distp(float p0, float p1, float p2, float sw, float4 sj){
    return fmaxf(fmaf(p0, sj.x, fmaf(p1, sj.y, fmaf(p2, sj.z, sw + sj.w))), 0.f);
}

// ---------------- GravNet aggregation: warm-started Illinois bracket + butterfly-rank endgame ----------------
__global__ __launch_bounds__(AGG_THREADS, 1)
void k_agg(int k){
    extern __shared__ float smem[];
    float4* sv  = (float4*)smem;
    float4* hv0 = sv + NP;
    float4* hv1 = hv0 + NP;
    float4* hv2 = hv1 + NP;
    unsigned long long* pball = (unsigned long long*)(hv2 + NP);

    int ev  = blockIdx.x / NBPE;
    int sub = blockIdx.x % NBPE;
    const float* se = g_s + (size_t)ev*NP*3;
    const float* he = g_h + (size_t)ev*NP*12;

    for (int j = threadIdx.x; j < NP; j += AGG_THREADS){
        float a = se[j*3+0], b = se[j*3+1], c = se[j*3+2];
        float sq = fmaf(c, c, fmaf(b, b, a*a));
        sv[j] = make_float4(a, b, c, sq);
        const float* hr = he + j*12;
        hv0[j] = make_float4(hr[0], hr[1], hr[2],  hr[3]);
        hv1[j] = make_float4(hr[4], hr[5], hr[6],  hr[7]);
        hv2[j] = make_float4(hr[8], hr[9], hr[10], hr[11]);
    }
    __syncthreads();

    int warp = threadIdx.x >> 5, lane = threadIdx.x & 31;
    unsigned lmlt = (1u << lane) - 1u;
    unsigned long long* pbuf = pball + warp*32;
    int base = sub * NODES_PB;
    int cntn = min(NODES_PB, NP - base);

    float Tprev = -1.f;

    for (int ni = warp; ni < cntn; ni += AGG_NW){
        int i = base + ni;
        float4 siv = sv[i];
        float p0 = -2.f*siv.x, p1 = -2.f*siv.y, p2 = -2.f*siv.z, sw = siv.w;

        unsigned long long selm = 0ull;
        {
            float f[64];
#pragma unroll
            for (int t=0; t<64; t++){
                f[t] = distp(p0, p1, p2, sw, sv[lane + t*32]);
            }
            unsigned mxu = 0u;
#pragma unroll
            for (int t=0; t<64; t++) mxu = umax(mxu, __float_as_uint(f[t]));
            mxu = __reduce_max_sync(0xFFFFFFFFu, mxu);

            float T = __uint_as_float(mxu);
            float selPiv = 0.f;
            bool exact = false, endg = false;
            float plo = 0.f, phi = 0.f;
            int needk = 0;

            if (mxu != 0u){
                float lo = 0.f, hi = __uint_as_float(mxu + 1u);
                int cLo = 0, cHi = NP;
                float wLo = 1.f, wHi = 1.f;
                float kh = (float)k - 0.5f;
                int iter = 0; bool first = true;
                while (__float_as_uint(hi) - __float_as_uint(lo) > 1u){
                    if (cHi - cLo <= PEEL_GAP){
                        endg = true; plo = lo; phi = hi; needk = k - cLo;
                        break;
                    }
                    float piv;
                    if (first && Tprev > 0.f){
                        piv = Tprev;
                    } else if ((iter & 7) == 7){
                        piv = __uint_as_float((__float_as_uint(lo) + __float_as_uint(hi)) >> 1);
                    } else {
                        float fLo = ((float)cLo - kh) * wLo;
                        float fHi = ((float)cHi - kh) * wHi;
                        piv = (lo*fHi - hi*fLo) / (fHi - fLo);
                    }
                    first = false;
                    unsigned pu  = __float_as_uint(piv);
                    unsigned lou = __float_as_uint(lo), hiu = __float_as_uint(hi);
                    if (pu <= lou) pu = lou + 1u;
                    if (pu >= hiu) pu = hiu - 1u;
                    piv = __uint_as_float(pu);
                    iter++;
                    int d0=0,d1=0,d2c=0,d3=0;
#pragma unroll
                    for (int t=0; t<64; t+=4){
                        d0  += (f[t]   < piv);
                        d1  += (f[t+1] < piv);
                        d2c += (f[t+2] < piv);
                        d3  += (f[t+3] < piv);
                    }
                    int c = __reduce_add_sync(0xFFFFFFFFu, (d0+d1)+(d2c+d3));
                    if (c == k){ exact = true; selPiv = piv; break; }
                    if (c < k){ lo = piv; cLo = c; wLo = 1.f; wHi *= 0.5f; }
                    else      { hi = piv; cHi = c; wHi = 1.f; wLo *= 0.5f; }
                }
                if (!exact && !endg) T = lo;
            }
            Tprev = exact ? selPiv : (endg ? phi : T);

            if (exact){
#pragma unroll
                for (int t=0; t<64; t++)
                    if (f[t] < selPiv) selm |= (1ull << t);
            } else if (endg){
                unsigned long long bm = 0ull;
#pragma unroll
                for (int t=0; t<64; t++){
                    bool lt = (f[t] < plo);
                    bool in = (!lt) && (f[t] < phi);
                    if (lt) selm |= (1ull << t);
                    if (in) bm   |= (1ull << t);
                }
                int cnt = __popcll(bm);
                int inc = cnt;
#pragma unroll
                for (int o=1; o<32; o<<=1){
                    int v = __shfl_up_sync(0xFFFFFFFFu, inc, o);
                    if (lane >= o) inc += v;
                }
                int off = inc - cnt;
                int nbr = __shfl_sync(0xFFFFFFFFu, inc, 31);
                {
                    unsigned long long b = bm; int o2 = off;
                    while (b){
                        int t = __ffsll((long long)b) - 1;
                        b &= b - 1ull;
                        float d2 = distp(p0, p1, p2, sw, sv[lane + t*32]);
                        pbuf[o2++] = ((unsigned long long)__float_as_uint(d2) << 32)
                                   | (unsigned)(t*32 + lane);
                    }
                }
                __syncwarp();
                unsigned long long mykey = (lane < nbr) ? pbuf[lane] : 0xFFFFFFFFFFFFFFFFull;
                int rank = 0;
#pragma unroll
                for (int s=1; s<32; s++){
                    unsigned long long o3 = __shfl_xor_sync(0xFFFFFFFFu, mykey, s);
                    rank += (o3 < mykey);
                }
                __syncwarp();
                pbuf[lane] = (lane < nbr && rank < needk) ? 1ull : 0ull;
                __syncwarp();
                {
                    unsigned long long b = bm; int o2 = off;
                    while (b){
                        int t = __ffsll((long long)b) - 1;
                        b &= b - 1ull;
                        if (pbuf[o2]) selm |= (1ull << t);
                        o2++;
                    }
                }
                __syncwarp();
            } else {
#pragma unroll
                for (int t=0; t<64; t++)
                    if (f[t] < T) selm |= (1ull << t);
                int m = __popc((unsigned)selm) + __popc((unsigned)(selm >> 32));
                m = __reduce_add_sync(0xFFFFFFFFu, m);
                int tiesleft = k - m;
                if (tiesleft > 0){
                    unsigned long long tm = 0ull;
#pragma unroll
                    for (int t=0; t<64; t++)
                        if (f[t] == T) tm |= (1ull << t);
                    unsigned tl = __reduce_or_sync(0xFFFFFFFFu, (unsigned)tm);
                    unsigned th = __reduce_or_sync(0xFFFFFFFFu, (unsigned)(tm >> 32));
                    unsigned long long anyt = ((unsigned long long)th << 32) | tl;
                    while (tiesleft > 0 && anyt){
                        int t = __ffsll((long long)anyt) - 1;
                        anyt &= anyt - 1ull;
                        unsigned tb = __ballot_sync(0xFFFFFFFFu, (tm >> t) & 1ull);
                        int nb = __popc(tb);
                        int take = nb < tiesleft ? nb : tiesleft;
                        if ((tb >> lane) & 1u){
                            if ((int)__popc(tb & lmlt) < take) selm |= (1ull << t);
                        }
                        tiesleft -= take;
                    }
                }
            }
        }

        float sm[12], mxv[12];
#pragma unroll
        for (int d=0; d<12; d++){ sm[d] = 0.f; mxv[d] = -3.4e38f; }
        unsigned long long rem = selm;
        while (rem){
            int t = __ffsll((long long)rem) - 1;
            rem &= rem - 1ull;
            int j = lane + t*32;
            float d2 = distp(p0, p1, p2, sw, sv[j]);
            float w = __expf(-10.f * d2);
            float4 h0 = hv0[j], h1 = hv1[j], h2 = hv2[j];
            float m;
            m=h0.x*w; sm[0]+=m;  mxv[0]=fmaxf(mxv[0],m);
            m=h0.y*w; sm[1]+=m;  mxv[1]=fmaxf(mxv[1],m);
            m=h0.z*w; sm[2]+=m;  mxv[2]=fmaxf(mxv[2],m);
            m=h0.w*w; sm[3]+=m;  mxv[3]=fmaxf(mxv[3],m);
            m=h1.x*w; sm[4]+=m;  mxv[4]=fmaxf(mxv[4],m);
            m=h1.y*w; sm[5]+=m;  mxv[5]=fmaxf(mxv[5],m);
            m=h1.z*w; sm[6]+=m;  mxv[6]=fmaxf(mxv[6],m);
            m=h1.w*w; sm[7]+=m;  mxv[7]=fmaxf(mxv[7],m);
            m=h2.x*w; sm[8]+=m;  mxv[8]=fmaxf(mxv[8],m);
            m=h2.y*w; sm[9]+=m;  mxv[9]=fmaxf(mxv[9],m);
            m=h2.z*w; sm[10]+=m; mxv[10]=fmaxf(mxv[10],m);
            m=h2.w*w; sm[11]+=m; mxv[11]=fmaxf(mxv[11],m);
        }
#pragma unroll
        for (int o=16; o; o>>=1){
#pragma unroll
            for (int d=0; d<12; d++){
                sm[d]  += __shfl_xor_sync(0xFFFFFFFFu, sm[d], o);
                mxv[d]  = fmaxf(mxv[d], __shfl_xor_sync(0xFFFFFFFFu, mxv[d], o));
            }
        }
        if (lane == 0){
            float invk = 1.f / (float)k;
            float* o = g_agg + ((size_t)ev*NP + i)*24;
#pragma unroll
            for (int d=0; d<12; d++){ o[d] = sm[d]*invk; o[12+d] = mxv[d]; }
        }
    }
}

// -------- post-GEMMs: full-chip parallel (128 blocks) --------
__global__ void k_post(const float* __restrict__ Wg1, const float* __restrict__ Wg2,
                       const float* __restrict__ bg2, const float* __restrict__ Wp1,
                       const float* __restrict__ bp1, const float* __restrict__ Wp2,
                       const float* __restrict__ bp2, int li){
    int n = blockIdx.x*blockDim.x + threadIdx.x;
    if (n >= NTOT) return;
    float xv[6], av[24], svv[3];
#pragma unroll
    for (int d=0; d<6;  d++) xv[d]  = g_x[n*6+d];
#pragma unroll
    for (int d=0; d<24; d++) av[d]  = g_agg[n*24+d];
#pragma unroll
    for (int d=0; d<3;  d++) svv[d] = g_s[n*3+d];
    const float* wg1 = Wg1 + li*144; const float* wg2 = Wg2 + li*576; const float* bgl = bg2 + li*24;
    const float* wp1 = Wp1 + li*162; const float* b1  = bp1 + li*6;
    const float* wp2 = Wp2 + li*36;  const float* b2  = bp2 + li*6;
    float outv[24];
#pragma unroll
    for (int c=0; c<24; c++){
        float a = __ldg(&bgl[c]);
#pragma unroll
        for (int d=0; d<6;  d++) a = fmaf(xv[d], __ldg(&wg1[d*24+c]), a);
#pragma unroll
        for (int e=0; e<24; e++) a = fmaf(av[e], __ldg(&wg2[e*24+c]), a);
        outv[c] = a;
    }
    float t1[6];
#pragma unroll
    for (int c=0; c<6; c++){
        float a = __ldg(&b1[c]);
#pragma unroll
        for (int d=0; d<24; d++) a = fmaf(outv[d], __ldg(&wp1[d*6+c]), a);
#pragma unroll
        for (int e=0; e<3;  e++) a = fmaf(svv[e], __ldg(&wp1[(24+e)*6+c]), a);
        t1[c] = elu1(a);
    }
#pragma unroll
    for (int c=0; c<6; c++){
        float a = __ldg(&b2[c]);
#pragma unroll
        for (int d=0; d<6; d++) a = fmaf(t1[d], __ldg(&wp2[d*6+c]), a);
        g_t[n*6+c] = elu1(a);
    }
}

// -------- per-event mean/min/max (16 blocks; serial final combine = R5-proven) --------
__global__ void k_stats(){
    int ev = blockIdx.x;
    float sm[6], mn[6], mx[6];
#pragma unroll
    for (int d=0; d<6; d++){ sm[d]=0.f; mn[d]=3.4e38f; mx[d]=-3.4e38f; }
    for (int j = threadIdx.x; j < NP; j += blockDim.x){
        const float* tr = g_t + ((size_t)ev*NP + j)*6;
#pragma unroll
        for (int d=0; d<6; d++){ float v = tr[d]; sm[d]+=v; mn[d]=fminf(mn[d],v); mx[d]=fmaxf(mx[d],v); }
    }
#pragma unroll
    for (int o=16; o; o>>=1){
#pragma unroll
        for (int d=0; d<6; d++){
            sm[d] += __shfl_xor_sync(0xFFFFFFFFu, sm[d], o);
            mn[d]  = fminf(mn[d], __shfl_xor_sync(0xFFFFFFFFu, mn[d], o));
            mx[d]  = fmaxf(mx[d], __shfl_xor_sync(0xFFFFFFFFu, mx[d], o));
        }
    }
    __shared__ float buf[16][18];
    int warp = threadIdx.x >> 5, lane = threadIdx.x & 31;
    if (lane == 0){
#pragma unroll
        for (int d=0; d<6; d++){ buf[warp][d]=sm[d]; buf[warp][6+d]=mn[d]; buf[warp][12+d]=mx[d]; }
    }
    __syncthreads();
    if (threadIdx.x == 0){
        float S[6], Mn[6], Mx[6];
#pragma unroll
        for (int d=0; d<6; d++){ S[d]=0.f; Mn[d]=3.4e38f; Mx[d]=-3.4e38f; }
        int nw = blockDim.x / 32;
        for (int w=0; w<nw; w++)
#pragma unroll
            for (int d=0; d<6; d++){ S[d]+=buf[w][d]; Mn[d]=fminf(Mn[d],buf[w][6+d]); Mx[d]=fmaxf(Mx[d],buf[w][12+d]); }
#pragma unroll
        for (int d=0; d<6; d++){
            g_stats[ev*18+d]    = S[d] * (1.f/(float)NP);
            g_stats[ev*18+6+d]  = Mn[d];
            g_stats[ev*18+12+d] = Mx[d];
        }
    }
}

// -------- global-exchange + next-layer s,h projection (128 blocks) --------
__global__ void k_exch(const float* __restrict__ Wex, const float* __restrict__ bex,
                       const float* __restrict__ Ws,  const float* __restrict__ bs,
                       const float* __restrict__ Wh,  const float* __restrict__ bh, int li){
    int n = blockIdx.x*blockDim.x + threadIdx.x;
    if (n >= NTOT) return;
    int ev = n >> 11;
    float exv[24];
#pragma unroll
    for (int d=0; d<18; d++) exv[d] = g_stats[ev*18+d];
#pragma unroll
    for (int d=0; d<6;  d++) exv[18+d] = g_t[n*6+d];
    const float* w = Wex + li*144; const float* b = bex + li*6;
    float xv[6];
#pragma unroll
    for (int c=0; c<6; c++){
        float a = __ldg(&b[c]);
#pragma unroll
        for (int d=0; d<24; d++) a = fmaf(exv[d], __ldg(&w[d*6+c]), a);
        float v = elu1(a);
        xv[c] = v;
        g_x[n*6+c] = v;
        g_y[n*24 + li*6 + c] = v;
    }
    if (li < 3) sh_from_x(xv, n, Ws, bs, Wh, bh, li+1);
}

__global__ __launch_bounds__(HT)
void k_head(const float* __restrict__ Wd0, const float* __restrict__ bd0,
            const float* __restrict__ Wd,  const float* __restrict__ bd,
            const float* __restrict__ Wh1, const float* __restrict__ bh1,
            const float* __restrict__ Wh2, const float* __restrict__ bh2,
            const float* __restrict__ Wh3, const float* __restrict__ bh3,
            const float* __restrict__ Wc,  const float* __restrict__ bc,
            const float* __restrict__ Wb,  const float* __restrict__ bb,
            float* __restrict__ out){
    __shared__ float sact[HT*65];
    int n = blockIdx.x*HT + threadIdx.x;
    float yv[24];
#pragma unroll
    for (int d=0; d<24; d++) yv[d] = g_y[n*24+d];
    float a6[6];
#pragma unroll
    for (int c=0; c<6; c++){
        float a = __ldg(&bd0[c]);
#pragma unroll
        for (int d=0; d<24; d++) a = fmaf(yv[d], __ldg(&Wd0[d*6+c]), a);
        a6[c] = elu1(a);
    }
#pragma unroll
    for (int j=0; j<3; j++){
        float b6[6];
#pragma unroll
        for (int c=0; c<6; c++){
            float a = __ldg(&bd[j*6+c]);
#pragma unroll
            for (int d=0; d<6; d++) a = fmaf(a6[d], __ldg(&Wd[j*36+d*6+c]), a);
            b6[c] = elu1(a);
        }
#pragma unroll
        for (int c=0; c<6; c++) a6[c] = b6[c];
    }
    float* my = sact + threadIdx.x*65;
#pragma unroll 4
    for (int c=0; c<64; c++){
        float a = __ldg(&bh1[c]);
#pragma unroll
        for (int d=0; d<6; d++) a = fmaf(a6[d], __ldg(&Wh1[d*64+c]), a);
        my[c] = elu1(a);
    }
    float acc[64];
#pragma unroll
    for (int c=0; c<64; c++) acc[c] = __ldg(&bh2[c]);
#pragma unroll 1
    for (int d=0; d<64; d++){
        float v = my[d];
#pragma unroll
        for (int c=0; c<64; c++) acc[c] = fmaf(v, __ldg(&Wh2[d*64+c]), acc[c]);
    }
#pragma unroll
    for (int c=0; c<64; c++) my[c] = elu1(acc[c]);
#pragma unroll
    for (int c=0; c<64; c++) acc[c] = __ldg(&bh3[c]);
#pragma unroll 1
    for (int d=0; d<64; d++){
        float v = my[d];
#pragma unroll
        for (int c=0; c<64; c++) acc[c] = fmaf(v, __ldg(&Wh3[d*64+c]), acc[c]);
    }
#pragma unroll
    for (int c=0; c<64; c++) my[c] = acc[c];
    float* o = out + (size_t)n*31;
#pragma unroll 2
    for (int c=0; c<30; c++){
        float a = __ldg(&bc[c]);
#pragma unroll 1
        for (int d=0; d<64; d++) a = fmaf(my[d], __ldg(&Wc[d*30+c]), a);
        o[c] = a;
    }
    {
        float a = __ldg(&bb[0]);
#pragma unroll 1
        for (int d=0; d<64; d++) a = fmaf(my[d], __ldg(&Wb[d]), a);
        o[30] = a;
    }
}

extern "C" void kernel_launch(void* const* d_in, const int* in_sizes, int n_in,
                              void* d_out, int out_size) {
    const float* x    = (const float*)d_in[0];
    const float* Win  = (const float*)d_in[1];
    const float* Ws   = (const float*)d_in[2];
    const float* bs   = (const float*)d_in[3];
    const float* Wh   = (const float*)d_in[4];
    const float* bh   = (const float*)d_in[5];
    const float* Wg1  = (const float*)d_in[6];
    const float* Wg2  = (const float*)d_in[7];
    const float* bg2  = (const float*)d_in[8];
    const float* Wp1  = (const float*)d_in[9];
    const float* bp1  = (const float*)d_in[10];
    const float* Wp2  = (const float*)d_in[11];
    const float* bp2  = (const float*)d_in[12];
    const float* Wex  = (const float*)d_in[13];
    const float* bex  = (const float*)d_in[14];
    const float* Wd0  = (const float*)d_in[15];
    const float* bd0  = (const float*)d_in[16];
    const float* Wd   = (const float*)d_in[17];
    const float* bd   = (const float*)d_in[18];
    const float* Wh1  = (const float*)d_in[19];
    const float* bh1  = (const float*)d_in[20];
    const float* Wh2  = (const float*)d_in[21];
    const float* bh2  = (const float*)d_in[22];
    const float* Wh3  = (const float*)d_in[23];
    const float* bh3  = (const float*)d_in[24];
    const float* Wc   = (const float*)d_in[25];
    const float* bc   = (const float*)d_in[26];
    const float* Wb   = (const float*)d_in[27];
    const float* bb   = (const float*)d_in[28];
    float* out = (float*)d_out;

    cudaFuncSetAttribute(k_agg, cudaFuncAttributeMaxDynamicSharedMemorySize, AGG_SMEM);

    const int KS[4] = {16, 128, 16, 256};
    int nb = (NTOT + 255)/256;

    k_embed<<<nb, 256>>>(x, Win, Ws, bs, Wh, bh);
    for (int li = 0; li < 4; li++){
        k_agg<<<NEV*NBPE, AGG_THREADS, AGG_SMEM>>>(KS[li]);
        k_post<<<nb, 256>>>(Wg1, Wg2, bg2, Wp1, bp1, Wp2, bp2, li);
        k_stats<<<NEV, 512>>>();
        k_exch<<<nb, 256>>>(Wex, bex, Ws, bs, Wh, bh, li);
    }
    k_head<<<NTOT/HT, HT>>>(Wd0, bd0, Wd, bd, Wh1, bh1, Wh2, bh2,
                            Wh3, bh3, Wc, bc, Wb, bb, out);
}